// round 9
// baseline (speedup 1.0000x reference)
#include <cuda_runtime.h>
#include <cuda_bf16.h>
#include <cstdint>

#define NN 10000
#define NE 160000
#define MS 128
#define MV 64
#define DIN 320
#define DK 64
#define NF 32
#define WN 384
#define MSGW 768   // m0[128] | m1 i-major [3][128] | m2 i-major [3][64] | m3[64]

// g_x1 layout: scalar [0..127] normal; vector part i-major: [128 + i*64 + u]
__device__ float g_x1[NN * DIN];
__device__ float g_msg[NN * MSGW];
__device__ uint4 g_twf[48 * 32 * 2];   // tpw B-fragments: [nt][lane][{hi,lo}]
__device__ uint4 g_kf[16 * 32];        // keys B-fragments: [nt*4+kc][lane]

// ---------------------------------------------------------------------------
__global__ void k_zero() {
    int i = blockIdx.x * blockDim.x + threadIdx.x;
    if (i < NN * MSGW / 4) ((float4*)g_msg)[i] = make_float4(0.f, 0.f, 0.f, 0.f);
}

// ---------------------------------------------------------------------------
static __device__ __forceinline__ uint32_t smem_u32(const void* p) {
    uint32_t a;
    asm("{ .reg .u64 t; cvta.to.shared.u64 t, %1; cvt.u32.u64 %0, t; }" : "=r"(a) : "l"(p));
    return a;
}
static __device__ __forceinline__ void bsplit(float v, __nv_bfloat16& h, __nv_bfloat16& l) {
    h = __float2bfloat16(v);
    l = __float2bfloat16(v - __bfloat162float(h));
}
static __device__ __forceinline__ void ldm4(uint32_t* r, uint32_t addr) {
    asm volatile("ldmatrix.sync.aligned.m8n8.x4.shared.b16 {%0,%1,%2,%3}, [%4];"
                 : "=r"(r[0]), "=r"(r[1]), "=r"(r[2]), "=r"(r[3]) : "r"(addr));
}
static __device__ __forceinline__ void ldm2t(uint32_t* r, uint32_t addr) {
    asm volatile("ldmatrix.sync.aligned.m8n8.x2.trans.shared.b16 {%0,%1}, [%2];"
                 : "=r"(r[0]), "=r"(r[1]) : "r"(addr));
}
static __device__ __forceinline__ void mma_bf16(float* c, const uint32_t* a, const uint32_t* b) {
    asm volatile(
        "mma.sync.aligned.m16n8k16.row.col.f32.bf16.bf16.f32 "
        "{%0,%1,%2,%3}, {%4,%5,%6,%7}, {%8,%9}, {%0,%1,%2,%3};"
        : "+f"(c[0]), "+f"(c[1]), "+f"(c[2]), "+f"(c[3])
        : "r"(a[0]), "r"(a[1]), "r"(a[2]), "r"(a[3]), "r"(b[0]), "r"(b[1]));
}
static __device__ __forceinline__ void redf(float* p, float v) {
    asm volatile("red.global.add.f32 [%0], %1;" :: "l"(p), "f"(v) : "memory");
}

// ---------------------------------------------------------------------------
// k_prep: build B fragments (validated ldm2t recipe), store lane-ordered.
// ---------------------------------------------------------------------------
#define PREP_SMEM 60416
__global__ void k_prep(const float* __restrict__ keys, const float* __restrict__ tpw) {
    extern __shared__ char smc[];
    __nv_bfloat16* twh = (__nv_bfloat16*)(smc);
    __nv_bfloat16* twl = (__nv_bfloat16*)(smc + 25088);
    __nv_bfloat16* kh  = (__nv_bfloat16*)(smc + 50176);
    __nv_bfloat16* kl  = (__nv_bfloat16*)(smc + 55296);

    int tid = threadIdx.x, lane = tid & 31;
    for (int idx = tid; idx < NF * WN; idx += 128) {
        int f = idx / WN, n = idx - f * WN;
        __nv_bfloat16 h, l;
        bsplit(tpw[idx], h, l);
        twh[f * 392 + n] = h;
        twl[f * 392 + n] = l;
    }
    for (int idx = tid; idx < DK * NF; idx += 128) {
        int kk = idx >> 5, f = idx & 31;
        __nv_bfloat16 h, l;
        bsplit(keys[f * DK + kk], h, l);
        kh[kk * 40 + f] = h;
        kl[kk * 40 + f] = l;
    }
    __syncthreads();

    if (tid < 32) {
        uint32_t twh_b = smem_u32(twh), twl_b = smem_u32(twl);
        uint32_t kh_b  = smem_u32(kh),  kl_b  = smem_u32(kl);
        uint32_t brow = (uint32_t)(lane & 15);
        for (int nt = 0; nt < 48; nt++) {
            int n0 = nt * 8;
            uint32_t bh0[2], bh1[2], bl0[2], bl1[2];
            ldm2t(bh0, twh_b + (brow * 392 + n0) * 2);
            ldm2t(bh1, twh_b + ((16 + brow) * 392 + n0) * 2);
            ldm2t(bl0, twl_b + (brow * 392 + n0) * 2);
            ldm2t(bl1, twl_b + ((16 + brow) * 392 + n0) * 2);
            g_twf[(nt * 32 + lane) * 2 + 0] = make_uint4(bh0[0], bh0[1], bh1[0], bh1[1]);
            g_twf[(nt * 32 + lane) * 2 + 1] = make_uint4(bl0[0], bl0[1], bl1[0], bl1[1]);
        }
        for (int nt = 0; nt < 4; nt++)
            for (int kc = 0; kc < 4; kc++) {
                uint32_t h2[2], l2[2];
                ldm2t(h2, kh_b + ((kc * 16 + brow) * 40 + nt * 8) * 2);
                ldm2t(l2, kl_b + ((kc * 16 + brow) * 40 + nt * 8) * 2);
                g_kf[(nt * 4 + kc) * 32 + lane] = make_uint4(h2[0], h2[1], l2[0], l2[1]);
            }
    }
}

// ---------------------------------------------------------------------------
// K1: both node linears, float4 A-loads. Vector part of g_x1 stored i-major.
// ---------------------------------------------------------------------------
#define K1_XP 324
#define K1S(AV0, AV1, KIDX) { \
    float4 w = *(const float4*)&ws[(KIDX) * MS + c0]; \
    acc[0][0] = fmaf(AV0, w.x, acc[0][0]); \
    acc[0][1] = fmaf(AV0, w.y, acc[0][1]); \
    acc[0][2] = fmaf(AV0, w.z, acc[0][2]); \
    acc[0][3] = fmaf(AV0, w.w, acc[0][3]); \
    acc[1][0] = fmaf(AV1, w.x, acc[1][0]); \
    acc[1][1] = fmaf(AV1, w.y, acc[1][1]); \
    acc[1][2] = fmaf(AV1, w.z, acc[1][2]); \
    acc[1][3] = fmaf(AV1, w.w, acc[1][3]); }
#define K1V(AV0, AV1, AV2, UIDX) { \
    float4 w = *(const float4*)&wv[(UIDX) * MV + v0]; \
    acc[0][0] = fmaf(AV0, w.x, acc[0][0]); \
    acc[0][1] = fmaf(AV0, w.y, acc[0][1]); \
    acc[0][2] = fmaf(AV0, w.z, acc[0][2]); \
    acc[0][3] = fmaf(AV0, w.w, acc[0][3]); \
    acc[1][0] = fmaf(AV1, w.x, acc[1][0]); \
    acc[1][1] = fmaf(AV1, w.y, acc[1][1]); \
    acc[1][2] = fmaf(AV1, w.z, acc[1][2]); \
    acc[1][3] = fmaf(AV1, w.w, acc[1][3]); \
    acc[2][0] = fmaf(AV2, w.x, acc[2][0]); \
    acc[2][1] = fmaf(AV2, w.y, acc[2][1]); \
    acc[2][2] = fmaf(AV2, w.z, acc[2][2]); \
    acc[2][3] = fmaf(AV2, w.w, acc[2][3]); }

__global__ __launch_bounds__(256, 2) void k1(
    const float* __restrict__ x,
    const float* __restrict__ Wsis, const float* __restrict__ Wsiv,
    const float* __restrict__ Wl1s, const float* __restrict__ Wl1v,
    float* __restrict__ out)
{
    extern __shared__ float sm[];
    float* xs = sm;
    float* ws = sm + 16 * K1_XP;
    float* wv = ws + MS * MS;

    int tid  = threadIdx.x;
    int base = blockIdx.x * 16;

    for (int idx = tid; idx < 16 * 80; idx += 256) {
        int r = idx / 80, c4 = idx - r * 80;
        float4 v = ((const float4*)(x + (size_t)(base + r) * DIN))[c4];
        *(float4*)&xs[r * K1_XP + c4 * 4] = v;
    }

    const int ct = tid & 31, nt = tid >> 5;
    const int c0 = ct * 4,  n0 = nt * 2;
    const int vt = tid & 15, rt = tid >> 4;
    const int v0 = vt * 4;

#pragma unroll 1
    for (int pass = 0; pass < 2; pass++) {
        const float* Ws = pass ? Wl1s : Wsis;
        const float* Wv = pass ? Wl1v : Wsiv;
        float* dst = pass ? g_x1 : out;

        __syncthreads();
        for (int idx = tid; idx < MS * MS / 4; idx += 256)
            ((float4*)ws)[idx] = ((const float4*)Ws)[idx];
        for (int idx = tid; idx < MV * MV / 4; idx += 256)
            ((float4*)wv)[idx] = ((const float4*)Wv)[idx];
        __syncthreads();

        // ---- scalar
        {
            float acc[2][4];
#pragma unroll
            for (int j = 0; j < 2; j++)
#pragma unroll
                for (int q = 0; q < 4; q++) acc[j][q] = 0.f;

            const float* a0p = &xs[n0 * K1_XP];
            const float* a1p = &xs[(n0 + 1) * K1_XP];
#pragma unroll 4
            for (int k4 = 0; k4 < MS / 4; k4++) {
                float4 A0 = *(const float4*)(a0p + 4 * k4);
                float4 A1 = *(const float4*)(a1p + 4 * k4);
                K1S(A0.x, A1.x, 4 * k4 + 0);
                K1S(A0.y, A1.y, 4 * k4 + 1);
                K1S(A0.z, A1.z, 4 * k4 + 2);
                K1S(A0.w, A1.w, 4 * k4 + 3);
            }
            const float sc = 0.08838834764831845f;
#pragma unroll
            for (int j = 0; j < 2; j++) {
                float4 o;
                o.x = acc[j][0] * sc; o.y = acc[j][1] * sc;
                o.z = acc[j][2] * sc; o.w = acc[j][3] * sc;
                *(float4*)&dst[(size_t)(base + n0 + j) * DIN + c0] = o;
            }
        }
        // ---- vector
        {
            float acc[3][4];
#pragma unroll
            for (int i = 0; i < 3; i++)
#pragma unroll
                for (int q = 0; q < 4; q++) acc[i][q] = 0.f;

            const float* bp = &xs[rt * K1_XP + MS];
#pragma unroll 4
            for (int u4 = 0; u4 < MV / 4; u4++) {
                float4 B0 = *(const float4*)(bp + 12 * u4);
                float4 B1 = *(const float4*)(bp + 12 * u4 + 4);
                float4 B2 = *(const float4*)(bp + 12 * u4 + 8);
                K1V(B0.x, B0.y, B0.z, 4 * u4 + 0);
                K1V(B0.w, B1.x, B1.y, 4 * u4 + 1);
                K1V(B1.z, B1.w, B2.x, 4 * u4 + 2);
                K1V(B2.y, B2.z, B2.w, 4 * u4 + 3);
            }
            const float sc = 0.125f;
            float* drow = dst + (size_t)(base + rt) * DIN + MS;
            if (pass == 0) {
#pragma unroll
                for (int i = 0; i < 3; i++)
#pragma unroll
                    for (int q = 0; q < 4; q++)
                        drow[3 * (v0 + q) + i] = acc[i][q] * sc;
            } else {
                // g_x1 vector part i-major: [i*64 + v]
#pragma unroll
                for (int i = 0; i < 3; i++) {
                    float4 o;
                    o.x = acc[i][0] * sc; o.y = acc[i][1] * sc;
                    o.z = acc[i][2] * sc; o.w = acc[i][3] * sc;
                    *(float4*)&drow[i * 64 + v0] = o;
                }
            }
        }
    }
}

// ---------------------------------------------------------------------------
// K2: warp-autonomous fused edge kernel, 8-edge slabs, 16 warps/SM.
// MMA A-rows duplicated via (lane&7) addressing; upper-half outputs unused.
// ---------------------------------------------------------------------------
#define SW_STRIDE 386
#define WREG_B    12352          // per-warp sw bytes (8 x 386 f32)
#define AUX_OFF   197632         // 16 x WREG_B
#define AUX_B     1280           // sph(640) + spl(640)
#define K2_SMEM   218112

__global__ __launch_bounds__(512, 1) void k2(
    const float* __restrict__ eq,  const float* __restrict__ esh,
    const int* __restrict__ esrc,  const int* __restrict__ edst)
{
    extern __shared__ char smc[];
    int tid = threadIdx.x, wid = tid >> 5, lane = tid & 31;

    char* swb = smc + wid * WREG_B;
    float* sw = (float*)swb;
    __nv_bfloat16* qh = (__nv_bfloat16*)swb;            // overlay: 8 rows, stride 72
    __nv_bfloat16* ql = (__nv_bfloat16*)(swb + 1152);
    char* aux = smc + AUX_OFF + wid * AUX_B;
    __nv_bfloat16* sph = (__nv_bfloat16*)aux;           // 8 rows, stride 40
    __nv_bfloat16* spl = (__nv_bfloat16*)(aux + 640);

    uint32_t qh_b = smem_u32(qh), ql_b = smem_u32(ql);
    uint32_t sph_b = smem_u32(sph), spl_b = smem_u32(spl);

    const int g = lane >> 2, t = lane & 3;
    const uint32_t adup = (uint32_t)(lane & 7);          // duplicated A-row
    const uint32_t acol = (uint32_t)((lane >> 4) * 8);
    const unsigned FULL = 0xffffffffu;

    int gw = blockIdx.x * 16 + wid;
    int wstride = gridDim.x * 16;

    for (int s = gw; s < NE / 8; s += wstride) {
        int ebase = s * 8;

        // ---- stage 8 q rows (x 1/8 logit scale) as bf16 hi/lo
#pragma unroll
        for (int e = 0; e < 8; e++) {
            float2 q2 = *(const float2*)(eq + (size_t)(ebase + e) * DK + lane * 2);
            __nv_bfloat16 h0, l0, h1, l1;
            bsplit(q2.x * 0.125f, h0, l0);
            bsplit(q2.y * 0.125f, h1, l1);
            __nv_bfloat162 hp; hp.x = h0; hp.y = h1;
            __nv_bfloat162 lp; lp.x = l0; lp.y = l1;
            *(__nv_bfloat162*)&qh[e * 72 + lane * 2] = hp;
            *(__nv_bfloat162*)&ql[e * 72 + lane * 2] = lp;
        }
        __syncwarp();

        // ---- MMA1: logits[8x32] (rows duplicated to 16) = q @ keys^T
        float c[4][4];
#pragma unroll
        for (int n = 0; n < 4; n++)
#pragma unroll
            for (int q = 0; q < 4; q++) c[n][q] = 0.f;
        {
            uint32_t Ah[4][4], Al[4][4];
#pragma unroll
            for (int kc = 0; kc < 4; kc++) {
                ldm4(Ah[kc], qh_b + (adup * 72 + kc * 16 + acol) * 2);
                ldm4(Al[kc], ql_b + (adup * 72 + kc * 16 + acol) * 2);
            }
#pragma unroll
            for (int n = 0; n < 4; n++)
#pragma unroll
                for (int kc = 0; kc < 4; kc++) {
                    uint4 kf = g_kf[(n * 4 + kc) * 32 + lane];
                    uint32_t bh[2] = {kf.x, kf.y};
                    uint32_t bl[2] = {kf.z, kf.w};
                    mma_bf16(c[n], Ah[kc], bh);
                    mma_bf16(c[n], Ah[kc], bl);
                    mma_bf16(c[n], Al[kc], bh);
                }
        }

        // ---- fragment softmax on rows 0-7 only (row g, quad lanes 4g..4g+3)
        {
            float v0[8];
#pragma unroll
            for (int n = 0; n < 4; n++) {
                v0[2 * n] = c[n][0]; v0[2 * n + 1] = c[n][1];
            }
            float m0 = v0[0];
#pragma unroll
            for (int q = 1; q < 8; q++) m0 = fmaxf(m0, v0[q]);
            m0 = fmaxf(m0, __shfl_xor_sync(FULL, m0, 1));
            m0 = fmaxf(m0, __shfl_xor_sync(FULL, m0, 2));
            float s0 = 0.f;
#pragma unroll
            for (int q = 0; q < 8; q++) { v0[q] = __expf(v0[q] - m0); s0 += v0[q]; }
            s0 += __shfl_xor_sync(FULL, s0, 1);
            s0 += __shfl_xor_sync(FULL, s0, 2);
            float i0 = __frcp_rn(s0);
#pragma unroll
            for (int n = 0; n < 4; n++) {
                __nv_bfloat16 h0, l0, h1, l1;
                bsplit(v0[2 * n] * i0, h0, l0);
                bsplit(v0[2 * n + 1] * i0, h1, l1);
                __nv_bfloat162 hp; hp.x = h0; hp.y = h1;
                __nv_bfloat162 lp; lp.x = l0; lp.y = l1;
                *(__nv_bfloat162*)&sph[g * 40 + n * 8 + 2 * t] = hp;
                *(__nv_bfloat162*)&spl[g * 40 + n * 8 + 2 * t] = lp;
            }
        }
        __syncwarp();

        // ---- MMA2: w[8x384] = p @ tpw (48 n-tiles, 3-pass hi/lo)
        {
            uint32_t Ph0[4], Ph1[4], Pl0[4], Pl1[4];
            ldm4(Ph0, sph_b + (adup * 40 + acol) * 2);
            ldm4(Ph1, sph_b + (adup * 40 + 16 + acol) * 2);
            ldm4(Pl0, spl_b + (adup * 40 + acol) * 2);
            ldm4(Pl1, spl_b + (adup * 40 + 16 + acol) * 2);

            uint4 bh = g_twf[(0 * 32 + lane) * 2 + 0];
            uint4 bl = g_twf[(0 * 32 + lane) * 2 + 1];
#pragma unroll 4
            for (int n = 0; n < 48; n++) {
                uint4 bhn, bln;
                if (n < 47) {
                    bhn = g_twf[((n + 1) * 32 + lane) * 2 + 0];
                    bln = g_twf[((n + 1) * 32 + lane) * 2 + 1];
                }
                uint32_t b0[2] = {bh.x, bh.y}, b1[2] = {bh.z, bh.w};
                uint32_t b2[2] = {bl.x, bl.y}, b3[2] = {bl.z, bl.w};
                float cc[4] = {0.f, 0.f, 0.f, 0.f};
                mma_bf16(cc, Ph0, b0);
                mma_bf16(cc, Ph1, b1);
                mma_bf16(cc, Ph0, b2);
                mma_bf16(cc, Ph1, b3);
                mma_bf16(cc, Pl0, b0);
                mma_bf16(cc, Pl1, b1);
                *(float2*)&sw[g * SW_STRIDE + n * 8 + 2 * t] = make_float2(cc[0], cc[1]);
                bh = bhn; bl = bln;
            }
        }
        __syncwarp();

        // ---- edge phase: 8 edges, direct coalesced scalar reds
#pragma unroll 2
        for (int e = 0; e < 8; e++) {
            int row = ebase + e;
            int src = __ldg(esrc + row);
            int dst = __ldg(edst + row);
            float4 sh = __ldg((const float4*)(esh + (size_t)row * 4));
            const float* xg = g_x1 + (size_t)src * DIN;
            const float* wr = sw + e * SW_STRIDE + lane;
            float* mrow = g_msg + (size_t)dst * MSGW + lane;

            float wa[12];
#pragma unroll
            for (int m = 0; m < 12; m++) wa[m] = wr[32 * m];

            float xsv[4];
#pragma unroll
            for (int m = 0; m < 4; m++) xsv[m] = xg[lane + 32 * m];
            float xv0[3], xv1[3];
#pragma unroll
            for (int i = 0; i < 3; i++) {
                xv0[i] = xg[MS + i * 64 + lane];
                xv1[i] = xg[MS + i * 64 + lane + 32];
            }

            // o0
#pragma unroll
            for (int m = 0; m < 4; m++)
                redf(mrow + 32 * m, wa[m] * xsv[m] * sh.x);
            // o1 (i-major)
#pragma unroll
            for (int m = 0; m < 4; m++) {
                float tt = wa[4 + m] * xsv[m];
                redf(mrow + 128 + 32 * m, tt * sh.y);
                redf(mrow + 256 + 32 * m, tt * sh.z);
                redf(mrow + 384 + 32 * m, tt * sh.w);
            }
            // o2 (i-major) + o3
            {
                float s20 = wa[8] * sh.x, s21 = wa[9] * sh.x;
                redf(mrow + 512,       s20 * xv0[0]);
                redf(mrow + 576,       s20 * xv0[1]);
                redf(mrow + 640,       s20 * xv0[2]);
                redf(mrow + 544,       s21 * xv1[0]);
                redf(mrow + 608,       s21 * xv1[1]);
                redf(mrow + 672,       s21 * xv1[2]);
                float d0 = xv0[0] * sh.y + xv0[1] * sh.z + xv0[2] * sh.w;
                float d1 = xv1[0] * sh.y + xv1[1] * sh.z + xv1[2] * sh.w;
                redf(mrow + 704, wa[10] * d0 * 0.5773502691896258f);
                redf(mrow + 736, wa[11] * d1 * 0.5773502691896258f);
            }
        }
        __syncwarp();
    }
}

// ---------------------------------------------------------------------------
// K3: output linear, float4 A-loads. 16 nodes/block, 2 blocks/SM.
// ---------------------------------------------------------------------------
#define K3_MP 772
#define K3S(AV0, AV1, KIDX) { \
    float4 w = *(const float4*)&ws[(KIDX) * MS + c0]; \
    acc[0][0] = fmaf(AV0, w.x, acc[0][0]); \
    acc[0][1] = fmaf(AV0, w.y, acc[0][1]); \
    acc[0][2] = fmaf(AV0, w.z, acc[0][2]); \
    acc[0][3] = fmaf(AV0, w.w, acc[0][3]); \
    acc[1][0] = fmaf(AV1, w.x, acc[1][0]); \
    acc[1][1] = fmaf(AV1, w.y, acc[1][1]); \
    acc[1][2] = fmaf(AV1, w.z, acc[1][2]); \
    acc[1][3] = fmaf(AV1, w.w, acc[1][3]); }
#define K3V(AV0, AV1, AV2, WP) { \
    float4 w = *(const float4*)(WP); \
    vacc[0][0] = fmaf(AV0, w.x, vacc[0][0]); \
    vacc[0][1] = fmaf(AV0, w.y, vacc[0][1]); \
    vacc[0][2] = fmaf(AV0, w.z, vacc[0][2]); \
    vacc[0][3] = fmaf(AV0, w.w, vacc[0][3]); \
    vacc[1][0] = fmaf(AV1, w.x, vacc[1][0]); \
    vacc[1][1] = fmaf(AV1, w.y, vacc[1][1]); \
    vacc[1][2] = fmaf(AV1, w.z, vacc[1][2]); \
    vacc[1][3] = fmaf(AV1, w.w, vacc[1][3]); \
    vacc[2][0] = fmaf(AV2, w.x, vacc[2][0]); \
    vacc[2][1] = fmaf(AV2, w.y, vacc[2][1]); \
    vacc[2][2] = fmaf(AV2, w.z, vacc[2][2]); \
    vacc[2][3] = fmaf(AV2, w.w, vacc[2][3]); }

__global__ __launch_bounds__(256, 2) void k3(
    const float* __restrict__ W2s0, const float* __restrict__ W2s3,
    const float* __restrict__ W2v1, const float* __restrict__ W2v2,
    float* __restrict__ out)
{
    extern __shared__ float sm[];
    float* ms = sm;                 // 16 x 772
    float* ws = sm + 16 * K3_MP;    // up to 128 x 128

    int tid  = threadIdx.x;
    int base = blockIdx.x * 16;

    for (int idx = tid; idx < 16 * 192; idx += 256) {
        int r = idx / 192, c4 = idx - r * 192;
        float4 v = ((const float4*)(g_msg + (size_t)(base + r) * MSGW))[c4];
        *(float4*)&ms[r * K3_MP + c4 * 4] = v;
    }
    for (int idx = tid; idx < MS * MS / 4; idx += 256)
        ((float4*)ws)[idx] = ((const float4*)W2s0)[idx];
    __syncthreads();

    const float sc = 0.007216878364870323f;   // 1/sqrt(192) / 10
    const int ct = tid & 31, nt = tid >> 5;
    const int c0 = ct * 4,  n0 = nt * 2;
    const int vt = tid & 15, rt = tid >> 4;
    const int v0 = vt * 4;

    float acc[2][4];
#pragma unroll
    for (int j = 0; j < 2; j++)
#pragma unroll
        for (int q = 0; q < 4; q++) acc[j][q] = 0.f;

    const float* a0p = &ms[n0 * K3_MP];
    const float* a1p = &ms[(n0 + 1) * K3_MP];
#pragma unroll 4
    for (int k4 = 0; k4 < MS / 4; k4++) {
        float4 A0 = *(const float4*)(a0p + 4 * k4);
        float4 A1 = *(const float4*)(a1p + 4 * k4);
        K3S(A0.x, A1.x, 4 * k4 + 0);
        K3S(A0.y, A1.y, 4 * k4 + 1);
        K3S(A0.z, A1.z, 4 * k4 + 2);
        K3S(A0.w, A1.w, 4 * k4 + 3);
    }
    __syncthreads();
    for (int idx = tid; idx < MV * MS / 4; idx += 256)
        ((float4*)ws)[idx] = ((const float4*)W2s3)[idx];
    __syncthreads();
#pragma unroll 4
    for (int k4 = 0; k4 < MV / 4; k4++) {
        float4 A0 = *(const float4*)(a0p + 704 + 4 * k4);
        float4 A1 = *(const float4*)(a1p + 704 + 4 * k4);
        K3S(A0.x, A1.x, 4 * k4 + 0);
        K3S(A0.y, A1.y, 4 * k4 + 1);
        K3S(A0.z, A1.z, 4 * k4 + 2);
        K3S(A0.w, A1.w, 4 * k4 + 3);
    }
#pragma unroll
    for (int j = 0; j < 2; j++) {
        float4* p = (float4*)&out[(size_t)(base + n0 + j) * DIN + c0];
        float4 o = *p;
        o.x += acc[j][0] * sc; o.y += acc[j][1] * sc;
        o.z += acc[j][2] * sc; o.w += acc[j][3] * sc;
        *p = o;
    }

    __syncthreads();
    for (int idx = tid; idx < MS * MV / 4; idx += 256)
        ((float4*)ws)[idx] = ((const float4*)W2v1)[idx];
    for (int idx = tid; idx < MV * MV / 4; idx += 256)
        ((float4*)(ws + MS * MV))[idx] = ((const float4*)W2v2)[idx];
    __syncthreads();

    {
        float vacc[3][4];
#pragma unroll
        for (int i = 0; i < 3; i++)
#pragma unroll
            for (int q = 0; q < 4; q++) vacc[i][q] = 0.f;

        const float* vp = &ms[rt * K3_MP];
#pragma unroll 2
        for (int k4 = 0; k4 < MS / 4; k4++) {
            float4 A0 = *(const float4*)(vp + MS + 0 * 128 + 4 * k4);
            float4 A1 = *(const float4*)(vp + MS + 1 * 128 + 4 * k4);
            float4 A2 = *(const float4*)(vp + MS + 2 * 128 + 4 * k4);
            K3V(A0.x, A1.x, A2.x, &ws[(4 * k4 + 0) * MV + v0]);
            K3V(A0.y, A1.y, A2.y, &ws[(4 * k4 + 1) * MV + v0]);
            K3V(A0.z, A1.z, A2.z, &ws[(4 * k4 + 2) * MV + v0]);
            K3V(A0.w, A1.w, A2.w, &ws[(4 * k4 + 3) * MV + v0]);
        }
#pragma unroll 2
        for (int k4 = 0; k4 < MV / 4; k4++) {
            float4 A0 = *(const float4*)(vp + 512 + 0 * 64 + 4 * k4);
            float4 A1 = *(const float4*)(vp + 512 + 1 * 64 + 4 * k4);
            float4 A2 = *(const float4*)(vp + 512 + 2 * 64 + 4 * k4);
            K3V(A0.x, A1.x, A2.x, &ws[MS * MV + (4 * k4 + 0) * MV + v0]);
            K3V(A0.y, A1.y, A2.y, &ws[MS * MV + (4 * k4 + 1) * MV + v0]);
            K3V(A0.z, A1.z, A2.z, &ws[MS * MV + (4 * k4 + 2) * MV + v0]);
            K3V(A0.w, A1.w, A2.w, &ws[MS * MV + (4 * k4 + 3) * MV + v0]);
        }
        float* drow = out + (size_t)(base + rt) * DIN + MS;
#pragma unroll
        for (int i = 0; i < 3; i++)
#pragma unroll
            for (int q = 0; q < 4; q++)
                drow[3 * (v0 + q) + i] += vacc[i][q] * sc;
    }
}

// ---------------------------------------------------------------------------
extern "C" void kernel_launch(void* const* d_in, const int* in_sizes, int n_in,
                              void* d_out, int out_size)
{
    const float* x    = (const float*)d_in[0];
    const float* eq   = (const float*)d_in[1];
    const float* esh  = (const float*)d_in[2];
    const float* Wsis = (const float*)d_in[3];
    const float* Wsiv = (const float*)d_in[4];
    const float* Wl1s = (const float*)d_in[5];
    const float* Wl1v = (const float*)d_in[6];
    const float* keys = (const float*)d_in[7];
    const float* tpw  = (const float*)d_in[8];
    const float* W2s0 = (const float*)d_in[9];
    const float* W2s3 = (const float*)d_in[10];
    const float* W2v1 = (const float*)d_in[11];
    const float* W2v2 = (const float*)d_in[12];
    const int*   esrc = (const int*)d_in[13];
    const int*   edst = (const int*)d_in[14];
    float* out = (float*)d_out;

    const int smem_k1 = (16 * K1_XP + MS * MS + MV * MV) * 4;
    const int smem_k3 = (16 * K3_MP + MS * MS) * 4;
    cudaFuncSetAttribute(k1, cudaFuncAttributeMaxDynamicSharedMemorySize, smem_k1);
    cudaFuncSetAttribute(k2, cudaFuncAttributeMaxDynamicSharedMemorySize, K2_SMEM);
    cudaFuncSetAttribute(k3, cudaFuncAttributeMaxDynamicSharedMemorySize, smem_k3);
    cudaFuncSetAttribute(k_prep, cudaFuncAttributeMaxDynamicSharedMemorySize, PREP_SMEM);

    k_zero<<<7500, 256>>>();
    k_prep<<<1, 128, PREP_SMEM>>>(keys, tpw);
    k1<<<625, 256, smem_k1>>>(x, Wsis, Wsiv, Wl1s, Wl1v, out);
    k2<<<148, 512, K2_SMEM>>>(eq, esh, esrc, edst);
    k3<<<625, 256, smem_k3>>>(W2s0, W2s3, W2v1, W2v2, out);
}

// round 12
// speedup vs baseline: 1.0582x; 1.0582x over previous
#include <cuda_runtime.h>
#include <cuda_bf16.h>
#include <cstdint>

#define NN 10000
#define NE 160000
#define MS 128
#define MV 64
#define DIN 320
#define DK 64
#define NF 32
#define WN 384
#define MSGW 768   // m0[128] | m1 i-major [3][128] | m2 i-major [3][64] | m3[64]

// g_x1 layout: scalar [0..127] normal; vector part i-major: [128 + i*64 + u]
__device__ float g_x1[NN * DIN];
__device__ float g_msg[NN * MSGW];
__device__ uint4 g_twf[48 * 32 * 2];   // tpw B-fragments: [nt][lane][{hi,lo}]
__device__ uint4 g_kf[16 * 32];        // keys B-fragments: [nt*4+kc][lane]

// ---------------------------------------------------------------------------
__global__ void k_zero() {
    int i = blockIdx.x * blockDim.x + threadIdx.x;
    if (i < NN * MSGW / 4) ((float4*)g_msg)[i] = make_float4(0.f, 0.f, 0.f, 0.f);
}

// ---------------------------------------------------------------------------
static __device__ __forceinline__ uint32_t smem_u32(const void* p) {
    uint32_t a;
    asm("{ .reg .u64 t; cvta.to.shared.u64 t, %1; cvt.u32.u64 %0, t; }" : "=r"(a) : "l"(p));
    return a;
}
static __device__ __forceinline__ void bsplit(float v, __nv_bfloat16& h, __nv_bfloat16& l) {
    h = __float2bfloat16(v);
    l = __float2bfloat16(v - __bfloat162float(h));
}
static __device__ __forceinline__ void ldm4(uint32_t* r, uint32_t addr) {
    asm volatile("ldmatrix.sync.aligned.m8n8.x4.shared.b16 {%0,%1,%2,%3}, [%4];"
                 : "=r"(r[0]), "=r"(r[1]), "=r"(r[2]), "=r"(r[3]) : "r"(addr));
}
static __device__ __forceinline__ void ldm2t(uint32_t* r, uint32_t addr) {
    asm volatile("ldmatrix.sync.aligned.m8n8.x2.trans.shared.b16 {%0,%1}, [%2];"
                 : "=r"(r[0]), "=r"(r[1]) : "r"(addr));
}
static __device__ __forceinline__ void mma_bf16(float* c, const uint32_t* a, const uint32_t* b) {
    asm volatile(
        "mma.sync.aligned.m16n8k16.row.col.f32.bf16.bf16.f32 "
        "{%0,%1,%2,%3}, {%4,%5,%6,%7}, {%8,%9}, {%0,%1,%2,%3};"
        : "+f"(c[0]), "+f"(c[1]), "+f"(c[2]), "+f"(c[3])
        : "r"(a[0]), "r"(a[1]), "r"(a[2]), "r"(a[3]), "r"(b[0]), "r"(b[1]));
}
// Sound form (R8-proven): volatile + memory clobber. The edge-phase software
// pipeline hoists next-edge loads into registers BEFORE the red burst in
// program order, so overlap survives the clobber.
static __device__ __forceinline__ void redf(float* p, float v) {
    asm volatile("red.global.add.f32 [%0], %1;" :: "l"(p), "f"(v) : "memory");
}

// ---------------------------------------------------------------------------
// k_prep: build B fragments (validated ldm2t recipe), store lane-ordered.
// ---------------------------------------------------------------------------
#define PREP_SMEM 60416
__global__ void k_prep(const float* __restrict__ keys, const float* __restrict__ tpw) {
    extern __shared__ char smc[];
    __nv_bfloat16* twh = (__nv_bfloat16*)(smc);
    __nv_bfloat16* twl = (__nv_bfloat16*)(smc + 25088);
    __nv_bfloat16* kh  = (__nv_bfloat16*)(smc + 50176);
    __nv_bfloat16* kl  = (__nv_bfloat16*)(smc + 55296);

    int tid = threadIdx.x, lane = tid & 31;
    for (int idx = tid; idx < NF * WN; idx += 128) {
        int f = idx / WN, n = idx - f * WN;
        __nv_bfloat16 h, l;
        bsplit(tpw[idx], h, l);
        twh[f * 392 + n] = h;
        twl[f * 392 + n] = l;
    }
    for (int idx = tid; idx < DK * NF; idx += 128) {
        int kk = idx >> 5, f = idx & 31;
        __nv_bfloat16 h, l;
        bsplit(keys[f * DK + kk], h, l);
        kh[kk * 40 + f] = h;
        kl[kk * 40 + f] = l;
    }
    __syncthreads();

    if (tid < 32) {
        uint32_t twh_b = smem_u32(twh), twl_b = smem_u32(twl);
        uint32_t kh_b  = smem_u32(kh),  kl_b  = smem_u32(kl);
        uint32_t brow = (uint32_t)(lane & 15);
        for (int nt = 0; nt < 48; nt++) {
            int n0 = nt * 8;
            uint32_t bh0[2], bh1[2], bl0[2], bl1[2];
            ldm2t(bh0, twh_b + (brow * 392 + n0) * 2);
            ldm2t(bh1, twh_b + ((16 + brow) * 392 + n0) * 2);
            ldm2t(bl0, twl_b + (brow * 392 + n0) * 2);
            ldm2t(bl1, twl_b + ((16 + brow) * 392 + n0) * 2);
            g_twf[(nt * 32 + lane) * 2 + 0] = make_uint4(bh0[0], bh0[1], bh1[0], bh1[1]);
            g_twf[(nt * 32 + lane) * 2 + 1] = make_uint4(bl0[0], bl0[1], bl1[0], bl1[1]);
        }
        for (int nt = 0; nt < 4; nt++)
            for (int kc = 0; kc < 4; kc++) {
                uint32_t h2[2], l2[2];
                ldm2t(h2, kh_b + ((kc * 16 + brow) * 40 + nt * 8) * 2);
                ldm2t(l2, kl_b + ((kc * 16 + brow) * 40 + nt * 8) * 2);
                g_kf[(nt * 4 + kc) * 32 + lane] = make_uint4(h2[0], h2[1], l2[0], l2[1]);
            }
    }
}

// ---------------------------------------------------------------------------
// K1: both node linears, float4 A-loads. Vector part of g_x1 stored i-major.
// ---------------------------------------------------------------------------
#define K1_XP 324
#define K1S(AV0, AV1, KIDX) { \
    float4 w = *(const float4*)&ws[(KIDX) * MS + c0]; \
    acc[0][0] = fmaf(AV0, w.x, acc[0][0]); \
    acc[0][1] = fmaf(AV0, w.y, acc[0][1]); \
    acc[0][2] = fmaf(AV0, w.z, acc[0][2]); \
    acc[0][3] = fmaf(AV0, w.w, acc[0][3]); \
    acc[1][0] = fmaf(AV1, w.x, acc[1][0]); \
    acc[1][1] = fmaf(AV1, w.y, acc[1][1]); \
    acc[1][2] = fmaf(AV1, w.z, acc[1][2]); \
    acc[1][3] = fmaf(AV1, w.w, acc[1][3]); }
#define K1V(AV0, AV1, AV2, UIDX) { \
    float4 w = *(const float4*)&wv[(UIDX) * MV + v0]; \
    acc[0][0] = fmaf(AV0, w.x, acc[0][0]); \
    acc[0][1] = fmaf(AV0, w.y, acc[0][1]); \
    acc[0][2] = fmaf(AV0, w.z, acc[0][2]); \
    acc[0][3] = fmaf(AV0, w.w, acc[0][3]); \
    acc[1][0] = fmaf(AV1, w.x, acc[1][0]); \
    acc[1][1] = fmaf(AV1, w.y, acc[1][1]); \
    acc[1][2] = fmaf(AV1, w.z, acc[1][2]); \
    acc[1][3] = fmaf(AV1, w.w, acc[1][3]); \
    acc[2][0] = fmaf(AV2, w.x, acc[2][0]); \
    acc[2][1] = fmaf(AV2, w.y, acc[2][1]); \
    acc[2][2] = fmaf(AV2, w.z, acc[2][2]); \
    acc[2][3] = fmaf(AV2, w.w, acc[2][3]); }

__global__ __launch_bounds__(256, 2) void k1(
    const float* __restrict__ x,
    const float* __restrict__ Wsis, const float* __restrict__ Wsiv,
    const float* __restrict__ Wl1s, const float* __restrict__ Wl1v,
    float* __restrict__ out)
{
    extern __shared__ float sm[];
    float* xs = sm;
    float* ws = sm + 16 * K1_XP;
    float* wv = ws + MS * MS;

    int tid  = threadIdx.x;
    int base = blockIdx.x * 16;

    for (int idx = tid; idx < 16 * 80; idx += 256) {
        int r = idx / 80, c4 = idx - r * 80;
        float4 v = ((const float4*)(x + (size_t)(base + r) * DIN))[c4];
        *(float4*)&xs[r * K1_XP + c4 * 4] = v;
    }

    const int ct = tid & 31, nt = tid >> 5;
    const int c0 = ct * 4,  n0 = nt * 2;
    const int vt = tid & 15, rt = tid >> 4;
    const int v0 = vt * 4;

#pragma unroll 1
    for (int pass = 0; pass < 2; pass++) {
        const float* Ws = pass ? Wl1s : Wsis;
        const float* Wv = pass ? Wl1v : Wsiv;
        float* dst = pass ? g_x1 : out;

        __syncthreads();
        for (int idx = tid; idx < MS * MS / 4; idx += 256)
            ((float4*)ws)[idx] = ((const float4*)Ws)[idx];
        for (int idx = tid; idx < MV * MV / 4; idx += 256)
            ((float4*)wv)[idx] = ((const float4*)Wv)[idx];
        __syncthreads();

        // ---- scalar
        {
            float acc[2][4];
#pragma unroll
            for (int j = 0; j < 2; j++)
#pragma unroll
                for (int q = 0; q < 4; q++) acc[j][q] = 0.f;

            const float* a0p = &xs[n0 * K1_XP];
            const float* a1p = &xs[(n0 + 1) * K1_XP];
#pragma unroll 4
            for (int k4 = 0; k4 < MS / 4; k4++) {
                float4 A0 = *(const float4*)(a0p + 4 * k4);
                float4 A1 = *(const float4*)(a1p + 4 * k4);
                K1S(A0.x, A1.x, 4 * k4 + 0);
                K1S(A0.y, A1.y, 4 * k4 + 1);
                K1S(A0.z, A1.z, 4 * k4 + 2);
                K1S(A0.w, A1.w, 4 * k4 + 3);
            }
            const float sc = 0.08838834764831845f;
#pragma unroll
            for (int j = 0; j < 2; j++) {
                float4 o;
                o.x = acc[j][0] * sc; o.y = acc[j][1] * sc;
                o.z = acc[j][2] * sc; o.w = acc[j][3] * sc;
                *(float4*)&dst[(size_t)(base + n0 + j) * DIN + c0] = o;
            }
        }
        // ---- vector
        {
            float acc[3][4];
#pragma unroll
            for (int i = 0; i < 3; i++)
#pragma unroll
                for (int q = 0; q < 4; q++) acc[i][q] = 0.f;

            const float* bp = &xs[rt * K1_XP + MS];
#pragma unroll 4
            for (int u4 = 0; u4 < MV / 4; u4++) {
                float4 B0 = *(const float4*)(bp + 12 * u4);
                float4 B1 = *(const float4*)(bp + 12 * u4 + 4);
                float4 B2 = *(const float4*)(bp + 12 * u4 + 8);
                K1V(B0.x, B0.y, B0.z, 4 * u4 + 0);
                K1V(B0.w, B1.x, B1.y, 4 * u4 + 1);
                K1V(B1.z, B1.w, B2.x, 4 * u4 + 2);
                K1V(B2.y, B2.z, B2.w, 4 * u4 + 3);
            }
            const float sc = 0.125f;
            float* drow = dst + (size_t)(base + rt) * DIN + MS;
            if (pass == 0) {
#pragma unroll
                for (int i = 0; i < 3; i++)
#pragma unroll
                    for (int q = 0; q < 4; q++)
                        drow[3 * (v0 + q) + i] = acc[i][q] * sc;
            } else {
                // g_x1 vector part i-major: [i*64 + v]
#pragma unroll
                for (int i = 0; i < 3; i++) {
                    float4 o;
                    o.x = acc[i][0] * sc; o.y = acc[i][1] * sc;
                    o.z = acc[i][2] * sc; o.w = acc[i][3] * sc;
                    *(float4*)&drow[i * 64 + v0] = o;
                }
            }
        }
    }
}

// ---------------------------------------------------------------------------
// K2: warp-autonomous fused edge kernel (R8 shape: 16-edge slabs, 8 warps).
// Edge phase software-pipelined; reds keep the sound memory clobber.
// ---------------------------------------------------------------------------
#define SW_STRIDE 386
#define WREG_B    24704          // per-warp w region bytes (16 x 386 f32)
#define AUX_OFF   197632         // 8 x WREG_B
#define AUX_B     2560
#define K2_SMEM   218112

__global__ __launch_bounds__(256, 1) void k2(
    const float* __restrict__ eq,  const float* __restrict__ esh,
    const int* __restrict__ esrc,  const int* __restrict__ edst)
{
    extern __shared__ char smc[];
    int tid = threadIdx.x, wid = tid >> 5, lane = tid & 31;

    char* swb = smc + wid * WREG_B;
    float* sw = (float*)swb;
    __nv_bfloat16* qh = (__nv_bfloat16*)swb;            // overlay, stride 72
    __nv_bfloat16* ql = (__nv_bfloat16*)(swb + 2304);
    char* aux = smc + AUX_OFF + wid * AUX_B;
    __nv_bfloat16* sph = (__nv_bfloat16*)aux;           // stride 40
    __nv_bfloat16* spl = (__nv_bfloat16*)(aux + 1280);

    uint32_t qh_b = smem_u32(qh), ql_b = smem_u32(ql);
    uint32_t sph_b = smem_u32(sph), spl_b = smem_u32(spl);

    const int g = lane >> 2, t = lane & 3;
    const uint32_t arow = (uint32_t)(lane & 15);
    const uint32_t acol = (uint32_t)((lane >> 4) * 8);
    const unsigned FULL = 0xffffffffu;

    int gw = blockIdx.x * 8 + wid;
    int wstride = gridDim.x * 8;

    for (int s = gw; s < NE / 16; s += wstride) {
        int ebase = s * 16;

        // ---- stage q (x 1/8 logit scale) as bf16 hi/lo
#pragma unroll
        for (int e = 0; e < 16; e++) {
            float2 q2 = *(const float2*)(eq + (size_t)(ebase + e) * DK + lane * 2);
            __nv_bfloat16 h0, l0, h1, l1;
            bsplit(q2.x * 0.125f, h0, l0);
            bsplit(q2.y * 0.125f, h1, l1);
            __nv_bfloat162 hp; hp.x = h0; hp.y = h1;
            __nv_bfloat162 lp; lp.x = l0; lp.y = l1;
            *(__nv_bfloat162*)&qh[e * 72 + lane * 2] = hp;
            *(__nv_bfloat162*)&ql[e * 72 + lane * 2] = lp;
        }
        __syncwarp();

        // ---- MMA1: logits[16x32] = q @ keys^T (3-pass hi/lo)
        float c[4][4];
#pragma unroll
        for (int n = 0; n < 4; n++)
#pragma unroll
            for (int q = 0; q < 4; q++) c[n][q] = 0.f;
        {
            uint32_t Ah[4][4], Al[4][4];
#pragma unroll
            for (int kc = 0; kc < 4; kc++) {
                ldm4(Ah[kc], qh_b + (arow * 72 + kc * 16 + acol) * 2);
                ldm4(Al[kc], ql_b + (arow * 72 + kc * 16 + acol) * 2);
            }
#pragma unroll
            for (int n = 0; n < 4; n++)
#pragma unroll
                for (int kc = 0; kc < 4; kc++) {
                    uint4 kf = g_kf[(n * 4 + kc) * 32 + lane];
                    uint32_t bh[2] = {kf.x, kf.y};
                    uint32_t bl[2] = {kf.z, kf.w};
                    mma_bf16(c[n], Ah[kc], bh);
                    mma_bf16(c[n], Ah[kc], bl);
                    mma_bf16(c[n], Al[kc], bh);
                }
        }

        // ---- fragment softmax: row r lives in lanes 4r..4r+3 (quad)
        {
            float v0[8], v1[8];
#pragma unroll
            for (int n = 0; n < 4; n++) {
                v0[2 * n] = c[n][0]; v0[2 * n + 1] = c[n][1];
                v1[2 * n] = c[n][2]; v1[2 * n + 1] = c[n][3];
            }
            float m0 = v0[0], m1 = v1[0];
#pragma unroll
            for (int q = 1; q < 8; q++) { m0 = fmaxf(m0, v0[q]); m1 = fmaxf(m1, v1[q]); }
            m0 = fmaxf(m0, __shfl_xor_sync(FULL, m0, 1));
            m0 = fmaxf(m0, __shfl_xor_sync(FULL, m0, 2));
            m1 = fmaxf(m1, __shfl_xor_sync(FULL, m1, 1));
            m1 = fmaxf(m1, __shfl_xor_sync(FULL, m1, 2));
            float s0 = 0.f, s1 = 0.f;
#pragma unroll
            for (int q = 0; q < 8; q++) {
                v0[q] = __expf(v0[q] - m0); s0 += v0[q];
                v1[q] = __expf(v1[q] - m1); s1 += v1[q];
            }
            s0 += __shfl_xor_sync(FULL, s0, 1);
            s0 += __shfl_xor_sync(FULL, s0, 2);
            s1 += __shfl_xor_sync(FULL, s1, 1);
            s1 += __shfl_xor_sync(FULL, s1, 2);
            float i0 = __frcp_rn(s0), i1 = __frcp_rn(s1);
#pragma unroll
            for (int n = 0; n < 4; n++) {
                __nv_bfloat16 h0, l0, h1, l1;
                bsplit(v0[2 * n] * i0, h0, l0);
                bsplit(v0[2 * n + 1] * i0, h1, l1);
                __nv_bfloat162 hp; hp.x = h0; hp.y = h1;
                __nv_bfloat162 lp; lp.x = l0; lp.y = l1;
                *(__nv_bfloat162*)&sph[g * 40 + n * 8 + 2 * t] = hp;
                *(__nv_bfloat162*)&spl[g * 40 + n * 8 + 2 * t] = lp;
                bsplit(v1[2 * n] * i1, h0, l0);
                bsplit(v1[2 * n + 1] * i1, h1, l1);
                hp.x = h0; hp.y = h1; lp.x = l0; lp.y = l1;
                *(__nv_bfloat162*)&sph[(g + 8) * 40 + n * 8 + 2 * t] = hp;
                *(__nv_bfloat162*)&spl[(g + 8) * 40 + n * 8 + 2 * t] = lp;
            }
        }
        __syncwarp();

        // ---- MMA2: w[16x384] = p @ tpw (48 n-tiles, 3-pass hi/lo)
        {
            uint32_t Ph0[4], Ph1[4], Pl0[4], Pl1[4];
            ldm4(Ph0, sph_b + (arow * 40 + acol) * 2);
            ldm4(Ph1, sph_b + (arow * 40 + 16 + acol) * 2);
            ldm4(Pl0, spl_b + (arow * 40 + acol) * 2);
            ldm4(Pl1, spl_b + (arow * 40 + 16 + acol) * 2);

            uint4 bh = g_twf[(0 * 32 + lane) * 2 + 0];
            uint4 bl = g_twf[(0 * 32 + lane) * 2 + 1];
#pragma unroll 4
            for (int n = 0; n < 48; n++) {
                uint4 bhn, bln;
                if (n < 47) {
                    bhn = g_twf[((n + 1) * 32 + lane) * 2 + 0];
                    bln = g_twf[((n + 1) * 32 + lane) * 2 + 1];
                }
                uint32_t b0[2] = {bh.x, bh.y}, b1[2] = {bh.z, bh.w};
                uint32_t b2[2] = {bl.x, bl.y}, b3[2] = {bl.z, bl.w};
                float cc[4] = {0.f, 0.f, 0.f, 0.f};
                mma_bf16(cc, Ph0, b0);
                mma_bf16(cc, Ph1, b1);
                mma_bf16(cc, Ph0, b2);
                mma_bf16(cc, Ph1, b3);
                mma_bf16(cc, Pl0, b0);
                mma_bf16(cc, Pl1, b1);
                int n0 = n * 8;
                *(float2*)&sw[g * SW_STRIDE + n0 + 2 * t]       = make_float2(cc[0], cc[1]);
                *(float2*)&sw[(g + 8) * SW_STRIDE + n0 + 2 * t] = make_float2(cc[2], cc[3]);
                bh = bhn; bl = bln;
            }
        }
        __syncwarp();

        // ---- edge phase: 16 edges, software-pipelined (double-buffered)
        {
            int   dstb[2];
            float4 shb[2];
            float xsb[2][4], xv0b[2][3], xv1b[2][3];

            // prologue: load edge 0 state into slot 0
            {
                int row = ebase;
                int src = __ldg(esrc + row);
                dstb[0] = __ldg(edst + row);
                shb[0] = __ldg((const float4*)(esh + (size_t)row * 4));
                const float* xg = g_x1 + (size_t)src * DIN;
#pragma unroll
                for (int m = 0; m < 4; m++) xsb[0][m] = xg[lane + 32 * m];
#pragma unroll
                for (int i = 0; i < 3; i++) {
                    xv0b[0][i] = xg[MS + i * 64 + lane];
                    xv1b[0][i] = xg[MS + i * 64 + lane + 32];
                }
            }

#pragma unroll 2
            for (int e = 0; e < 16; e++) {
                const int cur = e & 1, nxt = cur ^ 1;

                // prefetch edge e+1 into the other slot (issued before the
                // red burst in program order -> overlaps them on the scoreboard)
                if (e < 15) {
                    int row = ebase + e + 1;
                    int src = __ldg(esrc + row);
                    dstb[nxt] = __ldg(edst + row);
                    shb[nxt] = __ldg((const float4*)(esh + (size_t)row * 4));
                    const float* xg = g_x1 + (size_t)src * DIN;
#pragma unroll
                    for (int m = 0; m < 4; m++) xsb[nxt][m] = xg[lane + 32 * m];
#pragma unroll
                    for (int i = 0; i < 3; i++) {
                        xv0b[nxt][i] = xg[MS + i * 64 + lane];
                        xv1b[nxt][i] = xg[MS + i * 64 + lane + 32];
                    }
                }

                float4 sh = shb[cur];
                float* mrow = g_msg + (size_t)dstb[cur] * MSGW + lane;
                const float* wr = sw + e * SW_STRIDE + lane;

                float wa[12];
#pragma unroll
                for (int m = 0; m < 12; m++) wa[m] = wr[32 * m];

                // o0
#pragma unroll
                for (int m = 0; m < 4; m++)
                    redf(mrow + 32 * m, wa[m] * xsb[cur][m] * sh.x);
                // o1 (i-major)
#pragma unroll
                for (int m = 0; m < 4; m++) {
                    float tt = wa[4 + m] * xsb[cur][m];
                    redf(mrow + 128 + 32 * m, tt * sh.y);
                    redf(mrow + 256 + 32 * m, tt * sh.z);
                    redf(mrow + 384 + 32 * m, tt * sh.w);
                }
                // o2 (i-major) + o3
                {
                    float s20 = wa[8] * sh.x, s21 = wa[9] * sh.x;
                    redf(mrow + 512, s20 * xv0b[cur][0]);
                    redf(mrow + 576, s20 * xv0b[cur][1]);
                    redf(mrow + 640, s20 * xv0b[cur][2]);
                    redf(mrow + 544, s21 * xv1b[cur][0]);
                    redf(mrow + 608, s21 * xv1b[cur][1]);
                    redf(mrow + 672, s21 * xv1b[cur][2]);
                    float d0 = xv0b[cur][0] * sh.y + xv0b[cur][1] * sh.z + xv0b[cur][2] * sh.w;
                    float d1 = xv1b[cur][0] * sh.y + xv1b[cur][1] * sh.z + xv1b[cur][2] * sh.w;
                    redf(mrow + 704, wa[10] * d0 * 0.5773502691896258f);
                    redf(mrow + 736, wa[11] * d1 * 0.5773502691896258f);
                }
            }
        }
        __syncwarp();
    }
}

// ---------------------------------------------------------------------------
// K3: output linear, float4 A-loads. 16 nodes/block, 2 blocks/SM.
// ---------------------------------------------------------------------------
#define K3_MP 772
#define K3S(AV0, AV1, KIDX) { \
    float4 w = *(const float4*)&ws[(KIDX) * MS + c0]; \
    acc[0][0] = fmaf(AV0, w.x, acc[0][0]); \
    acc[0][1] = fmaf(AV0, w.y, acc[0][1]); \
    acc[0][2] = fmaf(AV0, w.z, acc[0][2]); \
    acc[0][3] = fmaf(AV0, w.w, acc[0][3]); \
    acc[1][0] = fmaf(AV1, w.x, acc[1][0]); \
    acc[1][1] = fmaf(AV1, w.y, acc[1][1]); \
    acc[1][2] = fmaf(AV1, w.z, acc[1][2]); \
    acc[1][3] = fmaf(AV1, w.w, acc[1][3]); }
#define K3V(AV0, AV1, AV2, WP) { \
    float4 w = *(const float4*)(WP); \
    vacc[0][0] = fmaf(AV0, w.x, vacc[0][0]); \
    vacc[0][1] = fmaf(AV0, w.y, vacc[0][1]); \
    vacc[0][2] = fmaf(AV0, w.z, vacc[0][2]); \
    vacc[0][3] = fmaf(AV0, w.w, vacc[0][3]); \
    vacc[1][0] = fmaf(AV1, w.x, vacc[1][0]); \
    vacc[1][1] = fmaf(AV1, w.y, vacc[1][1]); \
    vacc[1][2] = fmaf(AV1, w.z, vacc[1][2]); \
    vacc[1][3] = fmaf(AV1, w.w, vacc[1][3]); \
    vacc[2][0] = fmaf(AV2, w.x, vacc[2][0]); \
    vacc[2][1] = fmaf(AV2, w.y, vacc[2][1]); \
    vacc[2][2] = fmaf(AV2, w.z, vacc[2][2]); \
    vacc[2][3] = fmaf(AV2, w.w, vacc[2][3]); }

__global__ __launch_bounds__(256, 2) void k3(
    const float* __restrict__ W2s0, const float* __restrict__ W2s3,
    const float* __restrict__ W2v1, const float* __restrict__ W2v2,
    float* __restrict__ out)
{
    extern __shared__ float sm[];
    float* ms = sm;                 // 16 x 772
    float* ws = sm + 16 * K3_MP;    // up to 128 x 128

    int tid  = threadIdx.x;
    int base = blockIdx.x * 16;

    for (int idx = tid; idx < 16 * 192; idx += 256) {
        int r = idx / 192, c4 = idx - r * 192;
        float4 v = ((const float4*)(g_msg + (size_t)(base + r) * MSGW))[c4];
        *(float4*)&ms[r * K3_MP + c4 * 4] = v;
    }
    for (int idx = tid; idx < MS * MS / 4; idx += 256)
        ((float4*)ws)[idx] = ((const float4*)W2s0)[idx];
    __syncthreads();

    const float sc = 0.007216878364870323f;   // 1/sqrt(192) / 10
    const int ct = tid & 31, nt = tid >> 5;
    const int c0 = ct * 4,  n0 = nt * 2;
    const int vt = tid & 15, rt = tid >> 4;
    const int v0 = vt * 4;

    float acc[2][4];
#pragma unroll
    for (int j = 0; j < 2; j++)
#pragma unroll
        for (int q = 0; q < 4; q++) acc[j][q] = 0.f;

    const float* a0p = &ms[n0 * K3_MP];
    const float* a1p = &ms[(n0 + 1) * K3_MP];
#pragma unroll 4
    for (int k4 = 0; k4 < MS / 4; k4++) {
        float4 A0 = *(const float4*)(a0p + 4 * k4);
        float4 A1 = *(const float4*)(a1p + 4 * k4);
        K3S(A0.x, A1.x, 4 * k4 + 0);
        K3S(A0.y, A1.y, 4 * k4 + 1);
        K3S(A0.z, A1.z, 4 * k4 + 2);
        K3S(A0.w, A1.w, 4 * k4 + 3);
    }
    __syncthreads();
    for (int idx = tid; idx < MV * MS / 4; idx += 256)
        ((float4*)ws)[idx] = ((const float4*)W2s3)[idx];
    __syncthreads();
#pragma unroll 4
    for (int k4 = 0; k4 < MV / 4; k4++) {
        float4 A0 = *(const float4*)(a0p + 704 + 4 * k4);
        float4 A1 = *(const float4*)(a1p + 704 + 4 * k4);
        K3S(A0.x, A1.x, 4 * k4 + 0);
        K3S(A0.y, A1.y, 4 * k4 + 1);
        K3S(A0.z, A1.z, 4 * k4 + 2);
        K3S(A0.w, A1.w, 4 * k4 + 3);
    }
#pragma unroll
    for (int j = 0; j < 2; j++) {
        float4* p = (float4*)&out[(size_t)(base + n0 + j) * DIN + c0];
        float4 o = *p;
        o.x += acc[j][0] * sc; o.y += acc[j][1] * sc;
        o.z += acc[j][2] * sc; o.w += acc[j][3] * sc;
        *p = o;
    }

    __syncthreads();
    for (int idx = tid; idx < MS * MV / 4; idx += 256)
        ((float4*)ws)[idx] = ((const float4*)W2v1)[idx];
    for (int idx = tid; idx < MV * MV / 4; idx += 256)
        ((float4*)(ws + MS * MV))[idx] = ((const float4*)W2v2)[idx];
    __syncthreads();

    {
        float vacc[3][4];
#pragma unroll
        for (int i = 0; i < 3; i++)
#pragma unroll
            for (int q = 0; q < 4; q++) vacc[i][q] = 0.f;

        const float* vp = &ms[rt * K3_MP];
#pragma unroll 2
        for (int k4 = 0; k4 < MS / 4; k4++) {
            float4 A0 = *(const float4*)(vp + MS + 0 * 128 + 4 * k4);
            float4 A1 = *(const float4*)(vp + MS + 1 * 128 + 4 * k4);
            float4 A2 = *(const float4*)(vp + MS + 2 * 128 + 4 * k4);
            K3V(A0.x, A1.x, A2.x, &ws[(4 * k4 + 0) * MV + v0]);
            K3V(A0.y, A1.y, A2.y, &ws[(4 * k4 + 1) * MV + v0]);
            K3V(A0.z, A1.z, A2.z, &ws[(4 * k4 + 2) * MV + v0]);
            K3V(A0.w, A1.w, A2.w, &ws[(4 * k4 + 3) * MV + v0]);
        }
#pragma unroll 2
        for (int k4 = 0; k4 < MV / 4; k4++) {
            float4 A0 = *(const float4*)(vp + 512 + 0 * 64 + 4 * k4);
            float4 A1 = *(const float4*)(vp + 512 + 1 * 64 + 4 * k4);
            float4 A2 = *(const float4*)(vp + 512 + 2 * 64 + 4 * k4);
            K3V(A0.x, A1.x, A2.x, &ws[MS * MV + (4 * k4 + 0) * MV + v0]);
            K3V(A0.y, A1.y, A2.y, &ws[MS * MV + (4 * k4 + 1) * MV + v0]);
            K3V(A0.z, A1.z, A2.z, &ws[MS * MV + (4 * k4 + 2) * MV + v0]);
            K3V(A0.w, A1.w, A2.w, &ws[MS * MV + (4 * k4 + 3) * MV + v0]);
        }
        float* drow = out + (size_t)(base + rt) * DIN + MS;
#pragma unroll
        for (int i = 0; i < 3; i++)
#pragma unroll
            for (int q = 0; q < 4; q++)
                drow[3 * (v0 + q) + i] += vacc[i][q] * sc;
    }
}

// ---------------------------------------------------------------------------
extern "C" void kernel_launch(void* const* d_in, const int* in_sizes, int n_in,
                              void* d_out, int out_size)
{
    const float* x    = (const float*)d_in[0];
    const float* eq   = (const float*)d_in[1];
    const float* esh  = (const float*)d_in[2];
    const float* Wsis = (const float*)d_in[3];
    const float* Wsiv = (const float*)d_in[4];
    const float* Wl1s = (const float*)d_in[5];
    const float* Wl1v = (const float*)d_in[6];
    const float* keys = (const float*)d_in[7];
    const float* tpw  = (const float*)d_in[8];
    const float* W2s0 = (const float*)d_in[9];
    const float* W2s3 = (const float*)d_in[10];
    const float* W2v1 = (const float*)d_in[11];
    const float* W2v2 = (const float*)d_in[12];
    const int*   esrc = (const int*)d_in[13];
    const int*   edst = (const int*)d_in[14];
    float* out = (float*)d_out;

    const int smem_k1 = (16 * K1_XP + MS * MS + MV * MV) * 4;
    const int smem_k3 = (16 * K3_MP + MS * MS) * 4;
    cudaFuncSetAttribute(k1, cudaFuncAttributeMaxDynamicSharedMemorySize, smem_k1);
    cudaFuncSetAttribute(k2, cudaFuncAttributeMaxDynamicSharedMemorySize, K2_SMEM);
    cudaFuncSetAttribute(k3, cudaFuncAttributeMaxDynamicSharedMemorySize, smem_k3);
    cudaFuncSetAttribute(k_prep, cudaFuncAttributeMaxDynamicSharedMemorySize, PREP_SMEM);

    k_zero<<<7500, 256>>>();
    k_prep<<<1, 128, PREP_SMEM>>>(keys, tpw);
    k1<<<625, 256, smem_k1>>>(x, Wsis, Wsiv, Wl1s, Wl1v, out);
    k2<<<148, 256, K2_SMEM>>>(eq, esh, esrc, edst);
    k3<<<625, 256, smem_k3>>>(W2s0, W2s3, W2v1, W2v2, out);
}